// round 5
// baseline (speedup 1.0000x reference)
#include <cuda_runtime.h>
#include <math.h>

// Problem constants (fixed by the reference)
#define N_NODES 50000
#define N_EDGES 800000
#define NE_TOT  850000      // edges + self loops
#define F_IN    256
#define HEADS   2
#define C1      200
#define HC1     400
#define C2      100
#define HC2     200
#define NGRAPH  64
#define SLOPE   0.2f
#define EPS_GN  1e-5f

// ---------------- scratch: __device__ globals (alloc-free) ----------------
__device__ float4 g_xw1 [N_NODES * HC1 / 4];   // x @ W1
__device__ float4 g_c1  [N_NODES * HC1 / 4];   // conv1 accum -> relu(h)
__device__ float4 g_xw2 [N_NODES * HC2 / 4];   // h @ W2
__device__ float4 g_c2  [N_NODES * HC2 / 4];   // conv2 accum -> graphnorm temp
__device__ float2 g_als1[N_NODES], g_ald1[N_NODES], g_z1[N_NODES];   // [N][heads=2]
__device__ float2 g_als2[N_NODES], g_ald2[N_NODES], g_z2[N_NODES];
__device__ float2 g_p1[NE_TOT], g_p2[NE_TOT];
__device__ float  g_cnt [NGRAPH];
__device__ float  g_sum [NGRAPH * HC2], g_var[NGRAPH * HC2], g_pool[NGRAPH * HC2];
// decoded int32 indices (self-loops baked in)
__device__ int    g_src [NE_TOT], g_dst[NE_TOT];
__device__ int    g_batch[N_NODES];
__device__ int    g_is64;

// ---------------- detect input index width (int64 downcast-view vs int32) ----------------
// Reads edge_index as int32 words. If the data is really int64 (ids < 50000, >= 0),
// every odd 32-bit word is zero. If int32, odd words are random node ids (~0 prob all zero).
__global__ void detect_kernel(const int* __restrict__ ei)
{
    if (threadIdx.x == 0 && blockIdx.x == 0) {
        int any = 0;
        for (int k = 0; k < 256; k++) any |= ei[2 * k + 1];
        g_is64 = (any == 0) ? 1 : 0;
    }
}

// ---------------- decode indices to int32, append self loops ----------------
__global__ void convert_idx_kernel(const int* __restrict__ ei, const int* __restrict__ batch)
{
    int i = blockIdx.x * blockDim.x + threadIdx.x;
    int is64 = g_is64;
    if (i < NE_TOT) {
        if (i < N_EDGES) {
            g_src[i] = is64 ? ei[2 * i]               : ei[i];
            g_dst[i] = is64 ? ei[2 * (N_EDGES + i)]   : ei[N_EDGES + i];
        } else {
            int n = i - N_EDGES;
            g_src[i] = n; g_dst[i] = n;
        }
    }
    if (i < N_NODES) g_batch[i] = is64 ? batch[2 * i] : batch[i];
}

// ---------------- zero all accumulation buffers in one pass ----------------
#define Z_C1   (N_NODES * HC1 / 4)        // 5,000,000 float4
#define Z_C2   (N_NODES * HC2 / 4)        // 2,500,000
#define Z_G    (NGRAPH * HC2 / 4)         // 3,200
__global__ void zero_kernel()
{
    int i = blockIdx.x * blockDim.x + threadIdx.x;
    float4 z4 = make_float4(0.f, 0.f, 0.f, 0.f);
    float2 z2 = make_float2(0.f, 0.f);
    if (i < Z_C1) g_c1[i] = z4;
    if (i < Z_C2) g_c2[i] = z4;
    if (i < N_NODES) { g_z1[i] = z2; g_z2[i] = z2; }
    if (i < Z_G) ((float4*)g_sum)[i] = z4;
    if (i < Z_G) ((float4*)g_var)[i] = z4;
    if (i < Z_G) ((float4*)g_pool)[i] = z4;
    if (i < NGRAPH) g_cnt[i] = 0.f;
}

// ---------------- GEMM: C[M,Nc] = A[M,K] @ B[K,Nc], row-major ----------------
#define BM 128
#define BN 64
#define BK 16
#define TM 8
#define TN 4

template<int LAYER>
__global__ __launch_bounds__(256) void gemm_kernel(
    const float* __restrict__ Aext, const float* __restrict__ B)
{
    constexpr int M  = N_NODES;
    constexpr int Nc = (LAYER == 1) ? HC1 : HC2;
    constexpr int K  = (LAYER == 1) ? F_IN : HC1;
    const float* __restrict__ A = (LAYER == 1) ? Aext : (const float*)g_c1;
    float* __restrict__ C       = (LAYER == 1) ? (float*)g_xw1 : (float*)g_xw2;

    __shared__ float As[BK][BM];
    __shared__ float Bs[BK][BN];

    int tid = threadIdx.x;
    int tx = tid % 16;
    int ty = tid / 16;
    int row0 = blockIdx.y * BM;
    int col0 = blockIdx.x * BN;

    float acc[TM][TN];
#pragma unroll
    for (int i = 0; i < TM; i++)
#pragma unroll
        for (int j = 0; j < TN; j++) acc[i][j] = 0.f;

    for (int k0 = 0; k0 < K; k0 += BK) {
#pragma unroll
        for (int l = 0; l < (BM * BK) / 256; l++) {
            int idx = tid + l * 256;
            int m = idx / BK, kk = idx % BK;
            int gm = row0 + m;
            As[kk][m] = (gm < M) ? A[(size_t)gm * K + k0 + kk] : 0.f;
        }
#pragma unroll
        for (int l = 0; l < (BK * BN) / 256; l++) {
            int idx = tid + l * 256;
            int kk = idx / BN, n = idx % BN;
            int gn = col0 + n;
            Bs[kk][n] = (gn < Nc) ? B[(size_t)(k0 + kk) * Nc + gn] : 0.f;
        }
        __syncthreads();
#pragma unroll
        for (int kk = 0; kk < BK; kk++) {
            float a[TM], b[TN];
#pragma unroll
            for (int i = 0; i < TM; i++) a[i] = As[kk][ty * TM + i];
#pragma unroll
            for (int j = 0; j < TN; j++) b[j] = Bs[kk][tx * TN + j];
#pragma unroll
            for (int i = 0; i < TM; i++)
#pragma unroll
                for (int j = 0; j < TN; j++) acc[i][j] += a[i] * b[j];
        }
        __syncthreads();
    }
#pragma unroll
    for (int i = 0; i < TM; i++) {
        int gm = row0 + ty * TM + i;
        if (gm >= M) continue;
#pragma unroll
        for (int j = 0; j < TN; j++) {
            int gn = col0 + tx * TN + j;
            if (gn < Nc) C[(size_t)gm * Nc + gn] = acc[i][j];
        }
    }
}

// ---------------- per-node attention logits: one thread per (node, head) ----------------
template<int LAYER>
__global__ void attn_logits_kernel(const float* __restrict__ asrc, const float* __restrict__ adst)
{
    constexpr int HC = (LAYER == 1) ? HC1 : HC2;
    constexpr int C  = (LAYER == 1) ? C1 : C2;
    const float* __restrict__ xw = (LAYER == 1) ? (const float*)g_xw1 : (const float*)g_xw2;
    float2* __restrict__ als = (LAYER == 1) ? g_als1 : g_als2;
    float2* __restrict__ ald = (LAYER == 1) ? g_ald1 : g_ald2;

    int i = blockIdx.x * blockDim.x + threadIdx.x;
    if (i >= N_NODES * HEADS) return;
    int n = i >> 1, h = i & 1;
    const float4* row = (const float4*)(xw + (size_t)n * HC + h * C);
    const float4* va  = (const float4*)(asrc + h * C);
    const float4* vb  = (const float4*)(adst + h * C);
    float s = 0.f, t = 0.f;
#pragma unroll 5
    for (int c = 0; c < C / 4; c++) {
        float4 r = row[c], a = va[c], b = vb[c];
        s += r.x * a.x + r.y * a.y + r.z * a.z + r.w * a.w;
        t += r.x * b.x + r.y * b.y + r.z * b.z + r.w * b.w;
    }
    ((float*)als)[i] = s;
    ((float*)ald)[i] = t;
}

// ---------------- edge softmax numerator + denominator (no max shift; e is O(1)) ----------------
template<int LAYER>
__global__ void edge_soft_kernel()
{
    const float2* __restrict__ als = (LAYER == 1) ? g_als1 : g_als2;
    const float2* __restrict__ ald = (LAYER == 1) ? g_ald1 : g_ald2;
    float2* __restrict__ p = (LAYER == 1) ? g_p1 : g_p2;
    float2* __restrict__ z = (LAYER == 1) ? g_z1 : g_z2;

    int i = blockIdx.x * blockDim.x + threadIdx.x;
    if (i >= NE_TOT) return;
    int s = g_src[i], d = g_dst[i];
    float2 as_ = als[s];
    float2 ad  = ald[d];
    float e0 = as_.x + ad.x; e0 = (e0 > 0.f) ? e0 : SLOPE * e0;
    float e1 = as_.y + ad.y; e1 = (e1 > 0.f) ? e1 : SLOPE * e1;
    float p0 = __expf(e0), p1 = __expf(e1);
    p[i] = make_float2(p0, p1);
    atomicAdd(&z[d].x, p0);
    atomicAdd(&z[d].y, p1);
}

// ---------------- edge message scatter: out[d,:] += alpha * xw[s,:] (warp per edge) ----------------
template<int LAYER>
__global__ void edge_msg_kernel()
{
    constexpr int HC = (LAYER == 1) ? HC1 : HC2;
    constexpr int C  = (LAYER == 1) ? C1 : C2;
    const float* __restrict__ xw = (LAYER == 1) ? (const float*)g_xw1 : (const float*)g_xw2;
    const float2* __restrict__ p = (LAYER == 1) ? g_p1 : g_p2;
    const float2* __restrict__ z = (LAYER == 1) ? g_z1 : g_z2;
    float* __restrict__ out      = (LAYER == 1) ? (float*)g_c1 : (float*)g_c2;

    int w = (blockIdx.x * blockDim.x + threadIdx.x) >> 5;
    if (w >= NE_TOT) return;
    int lane = threadIdx.x & 31;
    int s = g_src[w], d = g_dst[w];
    float2 pp = p[w];
    float2 zz = z[d];
    float a0 = pp.x / zz.x;
    float a1 = pp.y / zz.y;
    const float* xr = xw + (size_t)s * HC;
    float* orow = out + (size_t)d * HC;
#pragma unroll
    for (int c = lane; c < HC; c += 32) {
        float a = (c < C) ? a0 : a1;
        atomicAdd(orow + c, a * xr[c]);
    }
}

// ---------------- h = relu(conv1 + b1), in place, float4 ----------------
__global__ void relu_bias_kernel(const float* __restrict__ bias)
{
    int i = blockIdx.x * blockDim.x + threadIdx.x;
    if (i >= N_NODES * HC1 / 4) return;
    int c = (i % (HC1 / 4)) * 4;
    float4 v = g_c1[i];
    v.x = fmaxf(v.x + bias[c + 0], 0.f);
    v.y = fmaxf(v.y + bias[c + 1], 0.f);
    v.z = fmaxf(v.z + bias[c + 2], 0.f);
    v.w = fmaxf(v.w + bias[c + 3], 0.f);
    g_c1[i] = v;
}

// ---------------- graph node counts ----------------
__global__ void counts_kernel()
{
    int n = blockIdx.x * blockDim.x + threadIdx.x;
    if (n >= N_NODES) return;
    atomicAdd(&g_cnt[g_batch[n]], 1.f);
}

// ---------------- GraphNorm pass 1: add conv2 bias, accumulate per-graph sum ----------------
__global__ void gn1_kernel(const float* __restrict__ b2)
{
    int i = blockIdx.x * blockDim.x + threadIdx.x;
    if (i >= N_NODES * HC2) return;
    int n = i / HC2, c = i % HC2;
    float* h = (float*)g_c2;
    float v = h[i] + b2[c];
    h[i] = v;
    atomicAdd(&g_sum[g_batch[n] * HC2 + c], v);
}

// ---------------- GraphNorm pass 2: t = x - mean*ms, accumulate var ----------------
__global__ void gn2_kernel(const float* __restrict__ ms)
{
    int i = blockIdx.x * blockDim.x + threadIdx.x;
    if (i >= N_NODES * HC2) return;
    int n = i / HC2, c = i % HC2;
    int g = g_batch[n];
    float* h = (float*)g_c2;
    float mean = g_sum[g * HC2 + c] / g_cnt[g];
    float t = h[i] - mean * ms[c];
    h[i] = t;
    atomicAdd(&g_var[g * HC2 + c], t * t);
}

// ---------------- GraphNorm pass 3: normalize, affine, relu, accumulate pool sum ----------------
__global__ void gn3_kernel(const float* __restrict__ w, const float* __restrict__ b)
{
    int i = blockIdx.x * blockDim.x + threadIdx.x;
    if (i >= N_NODES * HC2) return;
    int n = i / HC2, c = i % HC2;
    int g = g_batch[n];
    float v = ((const float*)g_c2)[i] * rsqrtf(g_var[g * HC2 + c] / g_cnt[g] + EPS_GN);
    v = w[c] * v + b[c];
    v = fmaxf(v, 0.f);
    atomicAdd(&g_pool[g * HC2 + c], v);
}

// ---------------- final: logits = (pool/cnt) @ lin_w + lin_b; sigmoid ----------------
__global__ void final_kernel(const float* __restrict__ lin_w, const float* __restrict__ lin_b,
                             float* __restrict__ out)
{
    int t = threadIdx.x;
    if (t >= NGRAPH * 2) return;
    int g = t / 2, k = t % 2;
    float acc = 0.f;
#pragma unroll 8
    for (int c = 0; c < HC2; c++)
        acc += g_pool[g * HC2 + c] * lin_w[c * 2 + k];
    float logit = acc / g_cnt[g] + lin_b[k];
    out[g * 2 + k] = 1.f / (1.f + __expf(-logit));
}

// ---------------- launch ----------------
extern "C" void kernel_launch(void* const* d_in, const int* in_sizes, int n_in,
                              void* d_out, int out_size)
{
    const float* x      = (const float*)d_in[0];
    const int*   ei     = (const int*)d_in[1];    // edge_index (int32 or int64-viewed)
    const int*   batch  = (const int*)d_in[2];
    const float* W1     = (const float*)d_in[3];
    const float* a_src1 = (const float*)d_in[4];
    const float* a_dst1 = (const float*)d_in[5];
    const float* b1     = (const float*)d_in[6];
    const float* W2     = (const float*)d_in[7];
    const float* a_src2 = (const float*)d_in[8];
    const float* a_dst2 = (const float*)d_in[9];
    const float* b2     = (const float*)d_in[10];
    const float* gn_w   = (const float*)d_in[11];
    const float* gn_b   = (const float*)d_in[12];
    const float* gn_ms  = (const float*)d_in[13];
    const float* lin_w  = (const float*)d_in[14];
    const float* lin_b  = (const float*)d_in[15];
    float*       out    = (float*)d_out;

    detect_kernel<<<1, 32>>>(ei);
    convert_idx_kernel<<<(NE_TOT + 255) / 256, 256>>>(ei, batch);
    zero_kernel<<<(Z_C1 + 255) / 256, 256>>>();

    // ---- layer 1 ----
    {
        dim3 grid((HC1 + BN - 1) / BN, (N_NODES + BM - 1) / BM);
        gemm_kernel<1><<<grid, 256>>>(x, W1);
    }
    attn_logits_kernel<1><<<(N_NODES * HEADS + 255) / 256, 256>>>(a_src1, a_dst1);
    edge_soft_kernel<1><<<(NE_TOT + 255) / 256, 256>>>();
    edge_msg_kernel<1><<<(NE_TOT * 32 + 255) / 256, 256>>>();
    relu_bias_kernel<<<(N_NODES * HC1 / 4 + 255) / 256, 256>>>(b1);

    // ---- layer 2 ----
    {
        dim3 grid((HC2 + BN - 1) / BN, (N_NODES + BM - 1) / BM);
        gemm_kernel<2><<<grid, 256>>>(nullptr, W2);
    }
    attn_logits_kernel<2><<<(N_NODES * HEADS + 255) / 256, 256>>>(a_src2, a_dst2);
    edge_soft_kernel<2><<<(NE_TOT + 255) / 256, 256>>>();
    edge_msg_kernel<2><<<(NE_TOT * 32 + 255) / 256, 256>>>();

    // ---- graphnorm + pool + head ----
    counts_kernel<<<(N_NODES + 255) / 256, 256>>>();
    gn1_kernel<<<(N_NODES * HC2 + 255) / 256, 256>>>(b2);
    gn2_kernel<<<(N_NODES * HC2 + 255) / 256, 256>>>(gn_ms);
    gn3_kernel<<<(N_NODES * HC2 + 255) / 256, 256>>>(gn_w, gn_b);
    final_kernel<<<1, 128>>>(lin_w, lin_b, out);
}

// round 6
// speedup vs baseline: 1.1522x; 1.1522x over previous
#include <cuda_runtime.h>
#include <math.h>

// Problem constants (fixed by the reference)
#define N_NODES 50000
#define N_EDGES 800000
#define NE_TOT  850000      // edges + self loops
#define F_IN    256
#define HEADS   2
#define C1      200
#define HC1     400
#define C2      100
#define HC2     200
#define NGRAPH  64
#define SLOPE   0.2f
#define EPS_GN  1e-5f

// ---------------- scratch: __device__ globals (alloc-free) ----------------
__device__ float4 g_xw1 [N_NODES * HC1 / 4];   // x @ W1
__device__ float4 g_c1  [N_NODES * HC1 / 4];   // conv1 accum (pre relu+bias)
__device__ float4 g_xw2 [N_NODES * HC2 / 4];   // relu(c1+b1) @ W2
__device__ float4 g_c2  [N_NODES * HC2 / 4];   // conv2 accum -> graphnorm temp
__device__ float2 g_als1[N_NODES], g_ald1[N_NODES], g_z1[N_NODES];   // [N][heads=2]
__device__ float2 g_als2[N_NODES], g_ald2[N_NODES], g_z2[N_NODES];
__device__ float2 g_p1[NE_TOT], g_p2[NE_TOT];
__device__ float  g_cnt [NGRAPH];
__device__ float  g_sum [NGRAPH * HC2], g_var[NGRAPH * HC2], g_pool[NGRAPH * HC2];
// decoded int32 indices (self-loops baked in)
__device__ int    g_src [NE_TOT], g_dst[NE_TOT];
__device__ int    g_batch[N_NODES];
__device__ int    g_is64;

// ---------------- detect input index width (int64 downcast-view vs int32) ----------------
__global__ void detect_kernel(const int* __restrict__ ei)
{
    if (threadIdx.x == 0 && blockIdx.x == 0) {
        int any = 0;
        for (int k = 0; k < 256; k++) any |= ei[2 * k + 1];
        g_is64 = (any == 0) ? 1 : 0;
    }
}

// ---------------- decode indices to int32, append self loops ----------------
__global__ void convert_idx_kernel(const int* __restrict__ ei, const int* __restrict__ batch)
{
    int i = blockIdx.x * blockDim.x + threadIdx.x;
    int is64 = g_is64;
    if (i < NE_TOT) {
        if (i < N_EDGES) {
            g_src[i] = is64 ? ei[2 * i]             : ei[i];
            g_dst[i] = is64 ? ei[2 * (N_EDGES + i)] : ei[N_EDGES + i];
        } else {
            int n = i - N_EDGES;
            g_src[i] = n; g_dst[i] = n;
        }
    }
    if (i < N_NODES) g_batch[i] = is64 ? batch[2 * i] : batch[i];
}

// ---------------- zero all accumulation buffers in one pass ----------------
#define Z_C1   (N_NODES * HC1 / 4)        // 5,000,000 float4
#define Z_C2   (N_NODES * HC2 / 4)        // 2,500,000
#define Z_G    (NGRAPH * HC2 / 4)         // 3,200
__global__ void zero_kernel()
{
    int i = blockIdx.x * blockDim.x + threadIdx.x;
    float4 z4 = make_float4(0.f, 0.f, 0.f, 0.f);
    float2 z2 = make_float2(0.f, 0.f);
    if (i < Z_C1) g_c1[i] = z4;
    if (i < Z_C2) g_c2[i] = z4;
    if (i < N_NODES) { g_z1[i] = z2; g_z2[i] = z2; }
    if (i < Z_G) { ((float4*)g_sum)[i] = z4; ((float4*)g_var)[i] = z4; ((float4*)g_pool)[i] = z4; }
    if (i < NGRAPH) g_cnt[i] = 0.f;
}

// ---------------- GEMM: C[M,Nc] = A[M,K] @ B[K,Nc], row-major ----------------
// 128x64 block tile, BK=16, 8x8 micro-tile, 128 threads.
// LAYER==2 fuses A := relu(c1 + b1) into the A-tile staging.
#define BM 128
#define BN 64
#define BK 16
#define TM 8
#define TN 8

template<int LAYER>
__global__ __launch_bounds__(128) void gemm_kernel(
    const float* __restrict__ Aext, const float* __restrict__ B, const float* __restrict__ biasK)
{
    constexpr int M  = N_NODES;
    constexpr int Nc = (LAYER == 1) ? HC1 : HC2;
    constexpr int K  = (LAYER == 1) ? F_IN : HC1;
    const float* __restrict__ A = (LAYER == 1) ? Aext : (const float*)g_c1;
    float* __restrict__ C       = (LAYER == 1) ? (float*)g_xw1 : (float*)g_xw2;

    __shared__ float As[BK][BM];
    __shared__ float Bs[BK][BN];

    int tid = threadIdx.x;
    int tx = tid % 8;           // 8 * TN(8) = 64 cols
    int ty = tid / 8;           // 16 * TM(8) = 128 rows
    int row0 = blockIdx.y * BM;
    int col0 = blockIdx.x * BN;

    float acc[TM][TN];
#pragma unroll
    for (int i = 0; i < TM; i++)
#pragma unroll
        for (int j = 0; j < TN; j++) acc[i][j] = 0.f;

    for (int k0 = 0; k0 < K; k0 += BK) {
        // A tile: 2048 elems / 128 threads = 16 scalar loads (coalesced on k)
#pragma unroll
        for (int l = 0; l < (BM * BK) / 128; l++) {
            int idx = tid + l * 128;
            int m = idx / BK, kk = idx % BK;
            int gm = row0 + m;
            float v = (gm < M) ? A[(size_t)gm * K + k0 + kk] : 0.f;
            if (LAYER == 2) v = fmaxf(v + __ldg(&biasK[k0 + kk]), 0.f);  // fused relu(c1+b1)
            As[kk][m] = v;
        }
        // B tile: 1024 elems / 128 threads = 2 float4 loads
#pragma unroll
        for (int l = 0; l < (BK * BN) / (128 * 4); l++) {
            int f = tid + l * 128;
            int kk = f / (BN / 4), nc = f % (BN / 4);
            int gn = col0 + nc * 4;
            float4 v = make_float4(0.f, 0.f, 0.f, 0.f);
            if (gn + 4 <= Nc) v = *(const float4*)&B[(size_t)(k0 + kk) * Nc + gn];
            *(float4*)&Bs[kk][nc * 4] = v;
        }
        __syncthreads();
#pragma unroll
        for (int kk = 0; kk < BK; kk++) {
            float4 a0 = *(const float4*)&As[kk][ty * TM + 0];
            float4 a1 = *(const float4*)&As[kk][ty * TM + 4];
            float4 b0 = *(const float4*)&Bs[kk][tx * TN + 0];
            float4 b1 = *(const float4*)&Bs[kk][tx * TN + 4];
            float a[TM] = {a0.x, a0.y, a0.z, a0.w, a1.x, a1.y, a1.z, a1.w};
            float b[TN] = {b0.x, b0.y, b0.z, b0.w, b1.x, b1.y, b1.z, b1.w};
#pragma unroll
            for (int i = 0; i < TM; i++)
#pragma unroll
                for (int j = 0; j < TN; j++) acc[i][j] += a[i] * b[j];
        }
        __syncthreads();
    }
#pragma unroll
    for (int i = 0; i < TM; i++) {
        int gm = row0 + ty * TM + i;
        if (gm >= M) continue;
#pragma unroll
        for (int j4 = 0; j4 < TN / 4; j4++) {
            int gn = col0 + tx * TN + j4 * 4;
            if (gn + 4 <= Nc) {
                float4 v = make_float4(acc[i][j4 * 4 + 0], acc[i][j4 * 4 + 1],
                                       acc[i][j4 * 4 + 2], acc[i][j4 * 4 + 3]);
                *(float4*)&C[(size_t)gm * Nc + gn] = v;
            }
        }
    }
}

// ---------------- per-node attention logits: one thread per (node, head) ----------------
template<int LAYER>
__global__ void attn_logits_kernel(const float* __restrict__ asrc, const float* __restrict__ adst)
{
    constexpr int HC = (LAYER == 1) ? HC1 : HC2;
    constexpr int C  = (LAYER == 1) ? C1 : C2;
    const float* __restrict__ xw = (LAYER == 1) ? (const float*)g_xw1 : (const float*)g_xw2;
    float2* __restrict__ als = (LAYER == 1) ? g_als1 : g_als2;
    float2* __restrict__ ald = (LAYER == 1) ? g_ald1 : g_ald2;

    int i = blockIdx.x * blockDim.x + threadIdx.x;
    if (i >= N_NODES * HEADS) return;
    int n = i >> 1, h = i & 1;
    const float4* row = (const float4*)(xw + (size_t)n * HC + h * C);
    const float4* va  = (const float4*)(asrc + h * C);
    const float4* vb  = (const float4*)(adst + h * C);
    float s = 0.f, t = 0.f;
#pragma unroll 5
    for (int c = 0; c < C / 4; c++) {
        float4 r = row[c], a = va[c], b = vb[c];
        s += r.x * a.x + r.y * a.y + r.z * a.z + r.w * a.w;
        t += r.x * b.x + r.y * b.y + r.z * b.z + r.w * b.w;
    }
    ((float*)als)[i] = s;
    ((float*)ald)[i] = t;
}

// ---------------- edge softmax numerator + denominator (no max shift; e is O(1)) ----------------
template<int LAYER>
__global__ void edge_soft_kernel()
{
    const float2* __restrict__ als = (LAYER == 1) ? g_als1 : g_als2;
    const float2* __restrict__ ald = (LAYER == 1) ? g_ald1 : g_ald2;
    float2* __restrict__ p = (LAYER == 1) ? g_p1 : g_p2;
    float2* __restrict__ z = (LAYER == 1) ? g_z1 : g_z2;

    int i = blockIdx.x * blockDim.x + threadIdx.x;
    if (i >= NE_TOT) return;
    int s = g_src[i], d = g_dst[i];
    float2 as_ = als[s];
    float2 ad  = ald[d];
    float e0 = as_.x + ad.x; e0 = (e0 > 0.f) ? e0 : SLOPE * e0;
    float e1 = as_.y + ad.y; e1 = (e1 > 0.f) ? e1 : SLOPE * e1;
    float p0 = __expf(e0), p1 = __expf(e1);
    p[i] = make_float2(p0, p1);
    atomicAdd(&z[d].x, p0);
    atomicAdd(&z[d].y, p1);
}

// ---------------- vector reduction: out[0..3] += v (global space asserted via cvta) ----------------
__device__ __forceinline__ void red_add_v4(float* addr, float4 v)
{
    unsigned long long ga = __cvta_generic_to_global(addr);
    asm volatile("red.global.add.v4.f32 [%0], {%1, %2, %3, %4};"
                 :: "l"(ga), "f"(v.x), "f"(v.y), "f"(v.z), "f"(v.w) : "memory");
}

// ---------------- edge message scatter: out[d,:] += alpha * xw[s,:] (warp per edge, float4) ----------------
template<int LAYER>
__global__ void edge_msg_kernel()
{
    constexpr int HC = (LAYER == 1) ? HC1 : HC2;
    constexpr int C  = (LAYER == 1) ? C1 : C2;
    const float4* __restrict__ xw = (LAYER == 1) ? (const float4*)g_xw1 : (const float4*)g_xw2;
    const float2* __restrict__ p = (LAYER == 1) ? g_p1 : g_p2;
    const float2* __restrict__ z = (LAYER == 1) ? g_z1 : g_z2;
    float* __restrict__ out      = (LAYER == 1) ? (float*)g_c1 : (float*)g_c2;

    int w = (blockIdx.x * blockDim.x + threadIdx.x) >> 5;
    if (w >= NE_TOT) return;
    int lane = threadIdx.x & 31;
    int s = g_src[w], d = g_dst[w];
    float2 pp = p[w];
    float2 zz = z[d];
    float a0 = pp.x / zz.x;
    float a1 = pp.y / zz.y;
    const float4* xr = xw + (size_t)s * (HC / 4);
    float* orow = out + (size_t)d * HC;
#pragma unroll
    for (int c4 = lane; c4 < HC / 4; c4 += 32) {
        float a = (c4 * 4 < C) ? a0 : a1;   // C divisible by 4: whole float4 in one head
        float4 v = __ldg(&xr[c4]);
        v.x *= a; v.y *= a; v.z *= a; v.w *= a;
        red_add_v4(orow + c4 * 4, v);
    }
}

// ---------------- graph node counts ----------------
__global__ void counts_kernel()
{
    int n = blockIdx.x * blockDim.x + threadIdx.x;
    if (n >= N_NODES) return;
    atomicAdd(&g_cnt[g_batch[n]], 1.f);
}

// ---------------- GraphNorm pass 1: add conv2 bias, accumulate per-graph sum ----------------
__global__ void gn1_kernel(const float* __restrict__ b2)
{
    int i = blockIdx.x * blockDim.x + threadIdx.x;
    if (i >= N_NODES * HC2) return;
    int n = i / HC2, c = i % HC2;
    float* h = (float*)g_c2;
    float v = h[i] + b2[c];
    h[i] = v;
    atomicAdd(&g_sum[g_batch[n] * HC2 + c], v);
}

// ---------------- GraphNorm pass 2: t = x - mean*ms, accumulate var ----------------
__global__ void gn2_kernel(const float* __restrict__ ms)
{
    int i = blockIdx.x * blockDim.x + threadIdx.x;
    if (i >= N_NODES * HC2) return;
    int n = i / HC2, c = i % HC2;
    int g = g_batch[n];
    float* h = (float*)g_c2;
    float mean = g_sum[g * HC2 + c] / g_cnt[g];
    float t = h[i] - mean * ms[c];
    h[i] = t;
    atomicAdd(&g_var[g * HC2 + c], t * t);
}

// ---------------- GraphNorm pass 3: normalize, affine, relu, accumulate pool sum ----------------
__global__ void gn3_kernel(const float* __restrict__ w, const float* __restrict__ b)
{
    int i = blockIdx.x * blockDim.x + threadIdx.x;
    if (i >= N_NODES * HC2) return;
    int n = i / HC2, c = i % HC2;
    int g = g_batch[n];
    float v = ((const float*)g_c2)[i] * rsqrtf(g_var[g * HC2 + c] / g_cnt[g] + EPS_GN);
    v = w[c] * v + b[c];
    v = fmaxf(v, 0.f);
    atomicAdd(&g_pool[g * HC2 + c], v);
}

// ---------------- final: logits = (pool/cnt) @ lin_w + lin_b; sigmoid ----------------
__global__ void final_kernel(const float* __restrict__ lin_w, const float* __restrict__ lin_b,
                             float* __restrict__ out)
{
    int t = threadIdx.x;
    if (t >= NGRAPH * 2) return;
    int g = t / 2, k = t % 2;
    float acc = 0.f;
#pragma unroll 8
    for (int c = 0; c < HC2; c++)
        acc += g_pool[g * HC2 + c] * lin_w[c * 2 + k];
    float logit = acc / g_cnt[g] + lin_b[k];
    out[g * 2 + k] = 1.f / (1.f + __expf(-logit));
}

// ---------------- launch ----------------
extern "C" void kernel_launch(void* const* d_in, const int* in_sizes, int n_in,
                              void* d_out, int out_size)
{
    const float* x      = (const float*)d_in[0];
    const int*   ei     = (const int*)d_in[1];    // edge_index (int32 or int64-viewed)
    const int*   batch  = (const int*)d_in[2];
    const float* W1     = (const float*)d_in[3];
    const float* a_src1 = (const float*)d_in[4];
    const float* a_dst1 = (const float*)d_in[5];
    const float* b1     = (const float*)d_in[6];
    const float* W2     = (const float*)d_in[7];
    const float* a_src2 = (const float*)d_in[8];
    const float* a_dst2 = (const float*)d_in[9];
    const float* b2     = (const float*)d_in[10];
    const float* gn_w   = (const float*)d_in[11];
    const float* gn_b   = (const float*)d_in[12];
    const float* gn_ms  = (const float*)d_in[13];
    const float* lin_w  = (const float*)d_in[14];
    const float* lin_b  = (const float*)d_in[15];
    float*       out    = (float*)d_out;

    detect_kernel<<<1, 32>>>(ei);
    convert_idx_kernel<<<(NE_TOT + 255) / 256, 256>>>(ei, batch);
    zero_kernel<<<(Z_C1 + 255) / 256, 256>>>();

    // ---- layer 1 ----
    {
        dim3 grid((HC1 + BN - 1) / BN, (N_NODES + BM - 1) / BM);
        gemm_kernel<1><<<grid, 128>>>(x, W1, nullptr);
    }
    attn_logits_kernel<1><<<(N_NODES * HEADS + 255) / 256, 256>>>(a_src1, a_dst1);
    edge_soft_kernel<1><<<(NE_TOT + 255) / 256, 256>>>();
    edge_msg_kernel<1><<<(NE_TOT * 32 + 255) / 256, 256>>>();

    // ---- layer 2 (relu(c1+b1) fused into A load) ----
    {
        dim3 grid((HC2 + BN - 1) / BN, (N_NODES + BM - 1) / BM);
        gemm_kernel<2><<<grid, 128>>>(nullptr, W2, b1);
    }
    attn_logits_kernel<2><<<(N_NODES * HEADS + 255) / 256, 256>>>(a_src2, a_dst2);
    edge_soft_kernel<2><<<(NE_TOT + 255) / 256, 256>>>();
    edge_msg_kernel<2><<<(NE_TOT * 32 + 255) / 256, 256>>>();

    // ---- graphnorm + pool + head ----
    counts_kernel<<<(N_NODES + 255) / 256, 256>>>();
    gn1_kernel<<<(N_NODES * HC2 + 255) / 256, 256>>>(b2);
    gn2_kernel<<<(N_NODES * HC2 + 255) / 256, 256>>>(gn_ms);
    gn3_kernel<<<(N_NODES * HC2 + 255) / 256, 256>>>(gn_w, gn_b);
    final_kernel<<<1, 128>>>(lin_w, lin_b, out);
}

// round 7
// speedup vs baseline: 1.7682x; 1.5346x over previous
#include <cuda_runtime.h>
#include <math.h>

// Problem constants (fixed by the reference)
#define N_NODES 50000
#define N_EDGES 800000
#define NE_TOT  850000      // edges + self loops
#define F_IN    256
#define HEADS   2
#define C1      200
#define HC1     400
#define C2      100
#define HC2     200
#define NGRAPH  64
#define SLOPE   0.2f
#define EPS_GN  1e-5f

#define SCAN_CHUNK 1024
#define NCHUNK ((N_NODES + SCAN_CHUNK - 1) / SCAN_CHUNK)   // 49

// ---------------- scratch: __device__ globals (alloc-free) ----------------
__device__ float4 g_xw1 [N_NODES * HC1 / 4];   // x @ W1
__device__ float4 g_c1  [N_NODES * HC1 / 4];   // h = relu(conv1 + b1)
__device__ float4 g_xw2 [N_NODES * HC2 / 4];   // h @ W2
__device__ float4 g_c2  [N_NODES * HC2 / 4];   // conv2 + b2
__device__ float2 g_als1[N_NODES], g_ald1[N_NODES];
__device__ float2 g_als2[N_NODES], g_ald2[N_NODES];
__device__ float  g_cnt [NGRAPH];
__device__ int    g_gstart[NGRAPH];
__device__ float  g_pool[NGRAPH * HC2];
// CSR by destination
__device__ int    g_src [NE_TOT], g_dst[NE_TOT];
__device__ int    g_deg [N_NODES], g_cur[N_NODES];
__device__ int    g_off [N_NODES + 1];
__device__ int    g_part[NCHUNK];
__device__ int    g_eid [NE_TOT];
__device__ int    g_batch[N_NODES];
__device__ int    g_is64;

// ---------------- detect input index width (int64 downcast-view vs int32) ----------------
__global__ void detect_kernel(const int* __restrict__ ei)
{
    if (threadIdx.x == 0 && blockIdx.x == 0) {
        int any = 0;
        for (int k = 0; k < 256; k++) any |= ei[2 * k + 1];
        g_is64 = (any == 0) ? 1 : 0;
    }
}

// ---------------- decode indices to int32, append self loops; zero counters ----------------
__global__ void convert_idx_kernel(const int* __restrict__ ei, const int* __restrict__ batch)
{
    int i = blockIdx.x * blockDim.x + threadIdx.x;
    int is64 = g_is64;
    if (i < NE_TOT) {
        if (i < N_EDGES) {
            g_src[i] = is64 ? ei[2 * i]             : ei[i];
            g_dst[i] = is64 ? ei[2 * (N_EDGES + i)] : ei[N_EDGES + i];
        } else {
            int n = i - N_EDGES;
            g_src[i] = n; g_dst[i] = n;
        }
    }
    if (i < N_NODES) {
        g_batch[i] = is64 ? batch[2 * i] : batch[i];
        g_deg[i] = 0; g_cur[i] = 0;
    }
    if (i < NGRAPH) g_cnt[i] = 0.f;
}

// ---------------- CSR build ----------------
__global__ void csr_count_kernel()
{
    int i = blockIdx.x * blockDim.x + threadIdx.x;
    if (i >= NE_TOT) return;
    atomicAdd(&g_deg[g_dst[i]], 1);
}

__global__ void scan1_kernel()
{
    __shared__ int buf[SCAN_CHUNK];
    int tid = threadIdx.x;
    int i = blockIdx.x * SCAN_CHUNK + tid;
    int v = (i < N_NODES) ? g_deg[i] : 0;
    buf[tid] = v;
    __syncthreads();
    for (int off = 1; off < SCAN_CHUNK; off <<= 1) {
        int t = (tid >= off) ? buf[tid - off] : 0;
        __syncthreads();
        buf[tid] += t;
        __syncthreads();
    }
    if (i < N_NODES) g_off[i] = buf[tid] - v;       // exclusive within chunk
    if (tid == SCAN_CHUNK - 1) g_part[blockIdx.x] = buf[tid];
}

__global__ void scan2_kernel()
{
    if (threadIdx.x == 0 && blockIdx.x == 0) {
        int run = 0;
        for (int b = 0; b < NCHUNK; b++) { int t = g_part[b]; g_part[b] = run; run += t; }
        g_off[N_NODES] = run;   // == NE_TOT
    }
}

__global__ void scan3_kernel()
{
    int i = blockIdx.x * blockDim.x + threadIdx.x;
    if (i < N_NODES) g_off[i] += g_part[i >> 10];
}

__global__ void csr_fill_kernel()
{
    int i = blockIdx.x * blockDim.x + threadIdx.x;
    if (i >= NE_TOT) return;
    int d = g_dst[i];
    int pos = atomicAdd(&g_cur[d], 1);
    g_eid[g_off[d] + pos] = i;
}

// ---------------- graph node counts + start offsets (batch is sorted) ----------------
__global__ void counts_kernel()
{
    int n = blockIdx.x * blockDim.x + threadIdx.x;
    if (n >= N_NODES) return;
    atomicAdd(&g_cnt[g_batch[n]], 1.f);
}

__global__ void graph_offsets_kernel()
{
    if (threadIdx.x == 0 && blockIdx.x == 0) {
        int off = 0;
        for (int g = 0; g < NGRAPH; g++) { g_gstart[g] = off; off += (int)g_cnt[g]; }
    }
}

// ---------------- GEMM: C[M,Nc] = A[M,K] @ B[K,Nc], row-major ----------------
// 128x128 block tile, BK=8, 8x8 micro-tile, 256 threads.
#define BM 128
#define BN 128
#define BK 8
#define TM 8
#define TN 8

template<int LAYER>
__global__ __launch_bounds__(256) void gemm_kernel(
    const float* __restrict__ Aext, const float* __restrict__ B)
{
    constexpr int M  = N_NODES;
    constexpr int Nc = (LAYER == 1) ? HC1 : HC2;
    constexpr int K  = (LAYER == 1) ? F_IN : HC1;
    const float* __restrict__ A = (LAYER == 1) ? Aext : (const float*)g_c1;
    float* __restrict__ C       = (LAYER == 1) ? (float*)g_xw1 : (float*)g_xw2;

    __shared__ float As[BK][BM + 4];
    __shared__ float Bs[BK][BN];

    int tid = threadIdx.x;
    int tx = tid % 16;          // 16 * TN(8) = 128 cols
    int ty = tid / 16;          // 16 * TM(8) = 128 rows
    int row0 = blockIdx.y * BM;
    int col0 = blockIdx.x * BN;

    float acc[TM][TN];
#pragma unroll
    for (int i = 0; i < TM; i++)
#pragma unroll
        for (int j = 0; j < TN; j++) acc[i][j] = 0.f;

    for (int k0 = 0; k0 < K; k0 += BK) {
        // A tile: 128 rows x 8 k = 256 float4 (one per thread)
        {
            int m = tid >> 1, f = tid & 1;
            int gm = row0 + m;
            float4 v = make_float4(0.f, 0.f, 0.f, 0.f);
            if (gm < M) v = *(const float4*)&A[(size_t)gm * K + k0 + f * 4];
            As[f * 4 + 0][m] = v.x;
            As[f * 4 + 1][m] = v.y;
            As[f * 4 + 2][m] = v.z;
            As[f * 4 + 3][m] = v.w;
        }
        // B tile: 8 k x 128 cols = 256 float4 (one per thread), coalesced
        {
            int kk = tid >> 5, nc4 = tid & 31;
            int gn = col0 + nc4 * 4;
            float4 v = make_float4(0.f, 0.f, 0.f, 0.f);
            if (gn + 4 <= Nc) v = *(const float4*)&B[(size_t)(k0 + kk) * Nc + gn];
            *(float4*)&Bs[kk][nc4 * 4] = v;
        }
        __syncthreads();
#pragma unroll
        for (int kk = 0; kk < BK; kk++) {
            float4 a0 = *(const float4*)&As[kk][ty * TM + 0];
            float4 a1 = *(const float4*)&As[kk][ty * TM + 4];
            float4 b0 = *(const float4*)&Bs[kk][tx * TN + 0];
            float4 b1 = *(const float4*)&Bs[kk][tx * TN + 4];
            float a[TM] = {a0.x, a0.y, a0.z, a0.w, a1.x, a1.y, a1.z, a1.w};
            float b[TN] = {b0.x, b0.y, b0.z, b0.w, b1.x, b1.y, b1.z, b1.w};
#pragma unroll
            for (int i = 0; i < TM; i++)
#pragma unroll
                for (int j = 0; j < TN; j++) acc[i][j] += a[i] * b[j];
        }
        __syncthreads();
    }
#pragma unroll
    for (int i = 0; i < TM; i++) {
        int gm = row0 + ty * TM + i;
        if (gm >= M) continue;
#pragma unroll
        for (int j4 = 0; j4 < TN / 4; j4++) {
            int gn = col0 + tx * TN + j4 * 4;
            if (gn + 4 <= Nc) {
                float4 v = make_float4(acc[i][j4 * 4 + 0], acc[i][j4 * 4 + 1],
                                       acc[i][j4 * 4 + 2], acc[i][j4 * 4 + 3]);
                *(float4*)&C[(size_t)gm * Nc + gn] = v;
            }
        }
    }
}

// ---------------- per-node attention logits: one thread per (node, head) ----------------
template<int LAYER>
__global__ void attn_logits_kernel(const float* __restrict__ asrc, const float* __restrict__ adst)
{
    constexpr int HC = (LAYER == 1) ? HC1 : HC2;
    constexpr int C  = (LAYER == 1) ? C1 : C2;
    const float* __restrict__ xw = (LAYER == 1) ? (const float*)g_xw1 : (const float*)g_xw2;
    float2* __restrict__ als = (LAYER == 1) ? g_als1 : g_als2;
    float2* __restrict__ ald = (LAYER == 1) ? g_ald1 : g_ald2;

    int i = blockIdx.x * blockDim.x + threadIdx.x;
    if (i >= N_NODES * HEADS) return;
    int n = i >> 1, h = i & 1;
    const float4* row = (const float4*)(xw + (size_t)n * HC + h * C);
    const float4* va  = (const float4*)(asrc + h * C);
    const float4* vb  = (const float4*)(adst + h * C);
    float s = 0.f, t = 0.f;
#pragma unroll 5
    for (int c = 0; c < C / 4; c++) {
        float4 r = row[c], a = va[c], b = vb[c];
        s += r.x * a.x + r.y * a.y + r.z * a.z + r.w * a.w;
        t += r.x * b.x + r.y * b.y + r.z * b.z + r.w * b.w;
    }
    ((float*)als)[i] = s;
    ((float*)ald)[i] = t;
}

// ---------------- fused attention aggregate: warp per destination node ----------------
// Pass A: z = sum_e exp(leakyrelu(als[s]+ald[d])) (warp reduction)
// Pass B: acc = sum_e alpha_e * xw[s]  (register accumulation, no atomics)
// Epilogue: LAYER1: c1 = relu(acc + b1); LAYER2: c2 = acc + b2
template<int LAYER>
__global__ __launch_bounds__(256) void attn_aggr_kernel(const float* __restrict__ bias)
{
    constexpr int HC4  = ((LAYER == 1) ? HC1 : HC2) / 4;  // 100 / 50
    constexpr int C4   = ((LAYER == 1) ? C1 : C2) / 4;    // 50 / 25
    constexpr int NACC = (HC4 + 31) / 32;                 // 4 / 2
    const float2* __restrict__ als = (LAYER == 1) ? g_als1 : g_als2;
    const float2* __restrict__ ald = (LAYER == 1) ? g_ald1 : g_ald2;
    const float4* __restrict__ xw  = (LAYER == 1) ? g_xw1 : g_xw2;
    float4* __restrict__ outv      = (LAYER == 1) ? g_c1 : g_c2;

    int warp = (blockIdx.x * blockDim.x + threadIdx.x) >> 5;
    if (warp >= N_NODES) return;
    int lane = threadIdx.x & 31;
    int d = warp;
    int off0 = g_off[d], off1 = g_off[d + 1];
    float2 ad = ald[d];

    // pass A: softmax denominator
    float z0 = 0.f, z1 = 0.f;
    for (int t = off0 + lane; t < off1; t += 32) {
        int s = g_src[g_eid[t]];
        float2 as_ = als[s];
        float e0 = as_.x + ad.x; e0 = (e0 > 0.f) ? e0 : SLOPE * e0;
        float e1 = as_.y + ad.y; e1 = (e1 > 0.f) ? e1 : SLOPE * e1;
        z0 += __expf(e0);
        z1 += __expf(e1);
    }
#pragma unroll
    for (int o = 16; o; o >>= 1) {
        z0 += __shfl_xor_sync(0xffffffffu, z0, o);
        z1 += __shfl_xor_sync(0xffffffffu, z1, o);
    }
    float inv0 = 1.f / z0, inv1 = 1.f / z1;

    // pass B: gather-accumulate (whole warp per edge)
    float4 acc[NACC];
#pragma unroll
    for (int r = 0; r < NACC; r++) acc[r] = make_float4(0.f, 0.f, 0.f, 0.f);

    for (int t = off0; t < off1; t++) {
        int s = g_src[g_eid[t]];          // uniform across warp (broadcast)
        float2 as_ = als[s];
        float e0 = as_.x + ad.x; e0 = (e0 > 0.f) ? e0 : SLOPE * e0;
        float e1 = as_.y + ad.y; e1 = (e1 > 0.f) ? e1 : SLOPE * e1;
        float a0 = __expf(e0) * inv0;
        float a1 = __expf(e1) * inv1;
        const float4* xr = xw + (size_t)s * HC4;
#pragma unroll
        for (int r = 0; r < NACC; r++) {
            int c4 = lane + 32 * r;
            if (c4 < HC4) {
                float a = (c4 < C4) ? a0 : a1;
                float4 v = __ldg(&xr[c4]);
                acc[r].x += a * v.x; acc[r].y += a * v.y;
                acc[r].z += a * v.z; acc[r].w += a * v.w;
            }
        }
    }

    // epilogue
    const float4* b4 = (const float4*)bias;
#pragma unroll
    for (int r = 0; r < NACC; r++) {
        int c4 = lane + 32 * r;
        if (c4 < HC4) {
            float4 b = b4[c4];
            float4 v;
            if (LAYER == 1) {
                v.x = fmaxf(acc[r].x + b.x, 0.f);
                v.y = fmaxf(acc[r].y + b.y, 0.f);
                v.z = fmaxf(acc[r].z + b.z, 0.f);
                v.w = fmaxf(acc[r].w + b.w, 0.f);
            } else {
                v.x = acc[r].x + b.x; v.y = acc[r].y + b.y;
                v.z = acc[r].z + b.z; v.w = acc[r].w + b.w;
            }
            outv[(size_t)d * HC4 + c4] = v;
        }
    }
}

// ---------------- fused GraphNorm + relu + mean-pool (batch sorted -> contiguous graphs) ----------------
// grid (NGRAPH, 2): block handles graph g, channels [blockIdx.y*100, +100). 128 threads, 100 active.
__global__ __launch_bounds__(128) void graphnorm_kernel(
    const float* __restrict__ gn_ms, const float* __restrict__ gn_w, const float* __restrict__ gn_b)
{
    int g = blockIdx.x;
    int c = blockIdx.y * (HC2 / 2) + threadIdx.x;
    if (threadIdx.x >= HC2 / 2) return;
    int n0 = g_gstart[g];
    float cntf = g_cnt[g];
    int n1 = n0 + (int)cntf;
    const float* h = (const float*)g_c2;

    float s = 0.f;
    for (int n = n0; n < n1; n++) s += h[(size_t)n * HC2 + c];
    float mean_ms = (s / cntf) * gn_ms[c];

    float var = 0.f;
    for (int n = n0; n < n1; n++) {
        float t = h[(size_t)n * HC2 + c] - mean_ms;
        var += t * t;
    }
    float scale = rsqrtf(var / cntf + EPS_GN);

    float w = gn_w[c], b = gn_b[c];
    float pool = 0.f;
    for (int n = n0; n < n1; n++) {
        float t = (h[(size_t)n * HC2 + c] - mean_ms) * scale;
        t = w * t + b;
        pool += fmaxf(t, 0.f);
    }
    g_pool[g * HC2 + c] = pool;
}

// ---------------- final: logits = (pool/cnt) @ lin_w + lin_b; sigmoid ----------------
__global__ void final_kernel(const float* __restrict__ lin_w, const float* __restrict__ lin_b,
                             float* __restrict__ out)
{
    int t = threadIdx.x;
    if (t >= NGRAPH * 2) return;
    int g = t / 2, k = t % 2;
    float acc = 0.f;
#pragma unroll 8
    for (int c = 0; c < HC2; c++)
        acc += g_pool[g * HC2 + c] * lin_w[c * 2 + k];
    float logit = acc / g_cnt[g] + lin_b[k];
    out[g * 2 + k] = 1.f / (1.f + __expf(-logit));
}

// ---------------- launch ----------------
extern "C" void kernel_launch(void* const* d_in, const int* in_sizes, int n_in,
                              void* d_out, int out_size)
{
    const float* x      = (const float*)d_in[0];
    const int*   ei     = (const int*)d_in[1];
    const int*   batch  = (const int*)d_in[2];
    const float* W1     = (const float*)d_in[3];
    const float* a_src1 = (const float*)d_in[4];
    const float* a_dst1 = (const float*)d_in[5];
    const float* b1     = (const float*)d_in[6];
    const float* W2     = (const float*)d_in[7];
    const float* a_src2 = (const float*)d_in[8];
    const float* a_dst2 = (const float*)d_in[9];
    const float* b2     = (const float*)d_in[10];
    const float* gn_w   = (const float*)d_in[11];
    const float* gn_b   = (const float*)d_in[12];
    const float* gn_ms  = (const float*)d_in[13];
    const float* lin_w  = (const float*)d_in[14];
    const float* lin_b  = (const float*)d_in[15];
    float*       out    = (float*)d_out;

    // index decode + CSR build + graph offsets
    detect_kernel<<<1, 32>>>(ei);
    convert_idx_kernel<<<(NE_TOT + 255) / 256, 256>>>(ei, batch);
    csr_count_kernel<<<(NE_TOT + 255) / 256, 256>>>();
    scan1_kernel<<<NCHUNK, SCAN_CHUNK>>>();
    scan2_kernel<<<1, 32>>>();
    scan3_kernel<<<(N_NODES + 255) / 256, 256>>>();
    csr_fill_kernel<<<(NE_TOT + 255) / 256, 256>>>();
    counts_kernel<<<(N_NODES + 255) / 256, 256>>>();
    graph_offsets_kernel<<<1, 32>>>();

    // ---- layer 1 ----
    {
        dim3 grid((HC1 + BN - 1) / BN, (N_NODES + BM - 1) / BM);
        gemm_kernel<1><<<grid, 256>>>(x, W1);
    }
    attn_logits_kernel<1><<<(N_NODES * HEADS + 255) / 256, 256>>>(a_src1, a_dst1);
    attn_aggr_kernel<1><<<(N_NODES * 32 + 255) / 256, 256>>>(b1);

    // ---- layer 2 ----
    {
        dim3 grid((HC2 + BN - 1) / BN, (N_NODES + BM - 1) / BM);
        gemm_kernel<2><<<grid, 256>>>(nullptr, W2);
    }
    attn_logits_kernel<2><<<(N_NODES * HEADS + 255) / 256, 256>>>(a_src2, a_dst2);
    attn_aggr_kernel<2><<<(N_NODES * 32 + 255) / 256, 256>>>(b2);

    // ---- graphnorm + pool + head ----
    {
        dim3 grid(NGRAPH, 2);
        graphnorm_kernel<<<grid, 128>>>(gn_ms, gn_w, gn_b);
    }
    final_kernel<<<1, 128>>>(lin_w, lin_b, out);
}

// round 8
// speedup vs baseline: 2.1302x; 1.2047x over previous
#include <cuda_runtime.h>
#include <math.h>

// Problem constants (fixed by the reference)
#define N_NODES 50000
#define N_EDGES 800000
#define NE_TOT  850000      // edges + self loops
#define F_IN    256
#define HEADS   2
#define C1      200
#define HC1     400
#define C2      100
#define HC2     200
#define NGRAPH  64
#define SLOPE   0.2f
#define EPS_GN  1e-5f

#define SCAN_CHUNK 1024
#define NCHUNK ((N_NODES + SCAN_CHUNK - 1) / SCAN_CHUNK)   // 49

// ---------------- scratch: __device__ globals (alloc-free) ----------------
__device__ float4 g_xw1 [N_NODES * HC1 / 4];   // x @ W1
__device__ float4 g_c1  [N_NODES * HC1 / 4];   // h = relu(conv1 + b1)
__device__ float4 g_xw2 [N_NODES * HC2 / 4];   // h @ W2
__device__ float4 g_c2  [N_NODES * HC2 / 4];   // conv2 + b2
__device__ float2 g_als1[N_NODES], g_ald1[N_NODES];
__device__ float2 g_als2[N_NODES], g_ald2[N_NODES];
__device__ float  g_cnt [NGRAPH];
__device__ int    g_gstart[NGRAPH];
__device__ float  g_pool[NGRAPH * HC2];
// CSR by destination
__device__ int    g_src [NE_TOT], g_dst[NE_TOT];
__device__ int    g_deg [N_NODES], g_cur[N_NODES];
__device__ int    g_off [N_NODES + 1];
__device__ int    g_part[NCHUNK];
__device__ int    g_ssrc[NE_TOT];              // src ids sorted by dst (direct, no eid indirection)
__device__ int    g_batch[N_NODES];
__device__ int    g_is64;

// ---------------- detect input index width (int64 downcast-view vs int32) ----------------
__global__ void detect_kernel(const int* __restrict__ ei)
{
    if (threadIdx.x == 0 && blockIdx.x == 0) {
        int any = 0;
        for (int k = 0; k < 256; k++) any |= ei[2 * k + 1];
        g_is64 = (any == 0) ? 1 : 0;
    }
}

// ---------------- decode indices to int32, append self loops; zero counters ----------------
__global__ void convert_idx_kernel(const int* __restrict__ ei, const int* __restrict__ batch)
{
    int i = blockIdx.x * blockDim.x + threadIdx.x;
    int is64 = g_is64;
    if (i < NE_TOT) {
        if (i < N_EDGES) {
            g_src[i] = is64 ? ei[2 * i]             : ei[i];
            g_dst[i] = is64 ? ei[2 * (N_EDGES + i)] : ei[N_EDGES + i];
        } else {
            int n = i - N_EDGES;
            g_src[i] = n; g_dst[i] = n;
        }
    }
    if (i < N_NODES) {
        g_batch[i] = is64 ? batch[2 * i] : batch[i];
        g_deg[i] = 0; g_cur[i] = 0;
    }
    if (i < NGRAPH) g_cnt[i] = 0.f;
}

// ---------------- CSR build ----------------
__global__ void csr_count_kernel()
{
    int i = blockIdx.x * blockDim.x + threadIdx.x;
    if (i >= NE_TOT) return;
    atomicAdd(&g_deg[g_dst[i]], 1);
}

__global__ void scan1_kernel()
{
    __shared__ int buf[SCAN_CHUNK];
    int tid = threadIdx.x;
    int i = blockIdx.x * SCAN_CHUNK + tid;
    int v = (i < N_NODES) ? g_deg[i] : 0;
    buf[tid] = v;
    __syncthreads();
    for (int off = 1; off < SCAN_CHUNK; off <<= 1) {
        int t = (tid >= off) ? buf[tid - off] : 0;
        __syncthreads();
        buf[tid] += t;
        __syncthreads();
    }
    if (i < N_NODES) g_off[i] = buf[tid] - v;       // exclusive within chunk
    if (tid == SCAN_CHUNK - 1) g_part[blockIdx.x] = buf[tid];
}

__global__ void scan2_kernel()
{
    if (threadIdx.x == 0 && blockIdx.x == 0) {
        int run = 0;
        for (int b = 0; b < NCHUNK; b++) { int t = g_part[b]; g_part[b] = run; run += t; }
        g_off[N_NODES] = run;   // == NE_TOT
    }
}

__global__ void scan3_kernel()
{
    int i = blockIdx.x * blockDim.x + threadIdx.x;
    if (i < N_NODES) g_off[i] += g_part[i >> 10];
}

__global__ void csr_fill_kernel()
{
    int i = blockIdx.x * blockDim.x + threadIdx.x;
    if (i >= NE_TOT) return;
    int d = g_dst[i];
    int pos = atomicAdd(&g_cur[d], 1);
    g_ssrc[g_off[d] + pos] = g_src[i];     // direct sorted-src (one less indirection later)
}

// ---------------- graph node counts + start offsets (batch is sorted) ----------------
__global__ void counts_kernel()
{
    int n = blockIdx.x * blockDim.x + threadIdx.x;
    if (n >= N_NODES) return;
    atomicAdd(&g_cnt[g_batch[n]], 1.f);
}

__global__ void graph_offsets_kernel()
{
    if (threadIdx.x == 0 && blockIdx.x == 0) {
        int off = 0;
        for (int g = 0; g < NGRAPH; g++) { g_gstart[g] = off; off += (int)g_cnt[g]; }
    }
}

// ---------------- GEMM: C[M,Nc] = A[M,K] @ B[K,Nc], row-major, double-buffered ----------------
// 128x128 block tile, BK=8, 8x8 micro-tile, 256 threads, 2-stage SMEM ping-pong.
#define BM 128
#define BN 128
#define BK 8
#define TM 8
#define TN 8

template<int LAYER>
__global__ __launch_bounds__(256) void gemm_kernel(
    const float* __restrict__ Aext, const float* __restrict__ B)
{
    constexpr int M  = N_NODES;
    constexpr int Nc = (LAYER == 1) ? HC1 : HC2;
    constexpr int K  = (LAYER == 1) ? F_IN : HC1;
    const float* __restrict__ A = (LAYER == 1) ? Aext : (const float*)g_c1;
    float* __restrict__ C       = (LAYER == 1) ? (float*)g_xw1 : (float*)g_xw2;

    __shared__ float As[2][BK][BM + 4];
    __shared__ float Bs[2][BK][BN];

    int tid = threadIdx.x;
    int tx = tid % 16;          // 16 * TN(8) = 128 cols
    int ty = tid / 16;          // 16 * TM(8) = 128 rows
    int row0 = blockIdx.y * BM;
    int col0 = blockIdx.x * BN;

    // per-thread staging coords
    int am = tid >> 1, af = tid & 1;          // A: row am, float4 slot af
    int bk = tid >> 5, bn4 = tid & 31;        // B: k row bk, float4 col bn4
    int agm = row0 + am;
    int bgn = col0 + bn4 * 4;

    float acc[TM][TN];
#pragma unroll
    for (int i = 0; i < TM; i++)
#pragma unroll
        for (int j = 0; j < TN; j++) acc[i][j] = 0.f;

    // prologue: stage 0
    {
        float4 av = make_float4(0.f, 0.f, 0.f, 0.f);
        if (agm < M) av = *(const float4*)&A[(size_t)agm * K + af * 4];
        As[0][af * 4 + 0][am] = av.x;
        As[0][af * 4 + 1][am] = av.y;
        As[0][af * 4 + 2][am] = av.z;
        As[0][af * 4 + 3][am] = av.w;
        float4 bv = make_float4(0.f, 0.f, 0.f, 0.f);
        if (bgn + 4 <= Nc) bv = *(const float4*)&B[(size_t)bk * Nc + bgn];
        *(float4*)&Bs[0][bk][bn4 * 4] = bv;
    }
    __syncthreads();

    constexpr int NSTEP = K / BK;
    int buf = 0;
#pragma unroll 4
    for (int s = 0; s < NSTEP; s++) {
        float4 av, bv;
        bool has_next = (s + 1 < NSTEP);
        if (has_next) {
            int k0 = (s + 1) * BK;
            av = make_float4(0.f, 0.f, 0.f, 0.f);
            if (agm < M) av = *(const float4*)&A[(size_t)agm * K + k0 + af * 4];
            bv = make_float4(0.f, 0.f, 0.f, 0.f);
            if (bgn + 4 <= Nc) bv = *(const float4*)&B[(size_t)(k0 + bk) * Nc + bgn];
        }
#pragma unroll
        for (int kk = 0; kk < BK; kk++) {
            float4 a0 = *(const float4*)&As[buf][kk][ty * TM + 0];
            float4 a1 = *(const float4*)&As[buf][kk][ty * TM + 4];
            float4 b0 = *(const float4*)&Bs[buf][kk][tx * TN + 0];
            float4 b1 = *(const float4*)&Bs[buf][kk][tx * TN + 4];
            float a[TM] = {a0.x, a0.y, a0.z, a0.w, a1.x, a1.y, a1.z, a1.w};
            float b[TN] = {b0.x, b0.y, b0.z, b0.w, b1.x, b1.y, b1.z, b1.w};
#pragma unroll
            for (int i = 0; i < TM; i++)
#pragma unroll
                for (int j = 0; j < TN; j++) acc[i][j] += a[i] * b[j];
        }
        if (has_next) {
            int nb = buf ^ 1;
            As[nb][af * 4 + 0][am] = av.x;
            As[nb][af * 4 + 1][am] = av.y;
            As[nb][af * 4 + 2][am] = av.z;
            As[nb][af * 4 + 3][am] = av.w;
            *(float4*)&Bs[nb][bk][bn4 * 4] = bv;
        }
        __syncthreads();
        buf ^= 1;
    }

#pragma unroll
    for (int i = 0; i < TM; i++) {
        int gm = row0 + ty * TM + i;
        if (gm >= M) continue;
#pragma unroll
        for (int j4 = 0; j4 < TN / 4; j4++) {
            int gn = col0 + tx * TN + j4 * 4;
            if (gn + 4 <= Nc) {
                float4 v = make_float4(acc[i][j4 * 4 + 0], acc[i][j4 * 4 + 1],
                                       acc[i][j4 * 4 + 2], acc[i][j4 * 4 + 3]);
                *(float4*)&C[(size_t)gm * Nc + gn] = v;
            }
        }
    }
}

// ---------------- per-node attention logits: one thread per (node, head) ----------------
template<int LAYER>
__global__ void attn_logits_kernel(const float* __restrict__ asrc, const float* __restrict__ adst)
{
    constexpr int HC = (LAYER == 1) ? HC1 : HC2;
    constexpr int C  = (LAYER == 1) ? C1 : C2;
    const float* __restrict__ xw = (LAYER == 1) ? (const float*)g_xw1 : (const float*)g_xw2;
    float2* __restrict__ als = (LAYER == 1) ? g_als1 : g_als2;
    float2* __restrict__ ald = (LAYER == 1) ? g_ald1 : g_ald2;

    int i = blockIdx.x * blockDim.x + threadIdx.x;
    if (i >= N_NODES * HEADS) return;
    int n = i >> 1, h = i & 1;
    const float4* row = (const float4*)(xw + (size_t)n * HC + h * C);
    const float4* va  = (const float4*)(asrc + h * C);
    const float4* vb  = (const float4*)(adst + h * C);
    float s = 0.f, t = 0.f;
#pragma unroll 5
    for (int c = 0; c < C / 4; c++) {
        float4 r = row[c], a = va[c], b = vb[c];
        s += r.x * a.x + r.y * a.y + r.z * a.z + r.w * a.w;
        t += r.x * b.x + r.y * b.y + r.z * b.z + r.w * b.w;
    }
    ((float*)als)[i] = s;
    ((float*)ald)[i] = t;
}

// ---------------- fused attention aggregate: 2 warps per destination node ----------------
// Each warp owns half the channels; softmax denominator (pass A) is recomputed per warp
// (8 B/edge — cheap). Pass B gathers with a 2-edge unroll for MLP, no atomics, single store.
template<int LAYER>
__global__ __launch_bounds__(256) void attn_aggr_kernel(const float* __restrict__ bias)
{
    constexpr int HC4   = ((LAYER == 1) ? HC1 : HC2) / 4;   // 100 / 50
    constexpr int C4    = ((LAYER == 1) ? C1 : C2) / 4;     // 50 / 25
    constexpr int PART4 = HC4 / 2;                          // 50 / 25 float4 per warp
    constexpr int NACC  = (PART4 + 31) / 32;                // 2 / 1
    const float2* __restrict__ als = (LAYER == 1) ? g_als1 : g_als2;
    const float2* __restrict__ ald = (LAYER == 1) ? g_ald1 : g_ald2;
    const float4* __restrict__ xw  = (LAYER == 1) ? g_xw1 : g_xw2;
    float4* __restrict__ outv      = (LAYER == 1) ? g_c1 : g_c2;

    int w = (blockIdx.x * blockDim.x + threadIdx.x) >> 5;
    int d    = w >> 1;            // node
    int part = w & 1;             // channel half
    if (d >= N_NODES) return;
    int lane = threadIdx.x & 31;
    int off0 = g_off[d], off1 = g_off[d + 1];
    float2 ad = ald[d];

    // pass A: softmax denominator (warp reduction)
    float z0 = 0.f, z1 = 0.f;
    for (int t = off0 + lane; t < off1; t += 32) {
        float2 as_ = als[g_ssrc[t]];
        float e0 = as_.x + ad.x; e0 = (e0 > 0.f) ? e0 : SLOPE * e0;
        float e1 = as_.y + ad.y; e1 = (e1 > 0.f) ? e1 : SLOPE * e1;
        z0 += __expf(e0);
        z1 += __expf(e1);
    }
#pragma unroll
    for (int o = 16; o; o >>= 1) {
        z0 += __shfl_xor_sync(0xffffffffu, z0, o);
        z1 += __shfl_xor_sync(0xffffffffu, z1, o);
    }
    float inv0 = 1.f / z0, inv1 = 1.f / z1;

    // pass B: gather-accumulate, 2-edge unroll
    float4 acc[NACC];
#pragma unroll
    for (int r = 0; r < NACC; r++) acc[r] = make_float4(0.f, 0.f, 0.f, 0.f);

    int cbase = part * PART4;
    int t = off0;
    for (; t + 1 < off1; t += 2) {
        int s0 = g_ssrc[t], s1 = g_ssrc[t + 1];
        float2 as0 = als[s0], as1 = als[s1];
        float e00 = as0.x + ad.x; e00 = (e00 > 0.f) ? e00 : SLOPE * e00;
        float e01 = as0.y + ad.y; e01 = (e01 > 0.f) ? e01 : SLOPE * e01;
        float e10 = as1.x + ad.x; e10 = (e10 > 0.f) ? e10 : SLOPE * e10;
        float e11 = as1.y + ad.y; e11 = (e11 > 0.f) ? e11 : SLOPE * e11;
        float a00 = __expf(e00) * inv0, a01 = __expf(e01) * inv1;
        float a10 = __expf(e10) * inv0, a11 = __expf(e11) * inv1;
        const float4* xr0 = xw + (size_t)s0 * HC4;
        const float4* xr1 = xw + (size_t)s1 * HC4;
#pragma unroll
        for (int r = 0; r < NACC; r++) {
            int c4 = cbase + lane + 32 * r;
            if (lane + 32 * r < PART4) {
                float aa = (c4 < C4) ? a00 : a01;
                float ab = (c4 < C4) ? a10 : a11;
                float4 v0 = __ldg(&xr0[c4]);
                float4 v1 = __ldg(&xr1[c4]);
                acc[r].x += aa * v0.x + ab * v1.x;
                acc[r].y += aa * v0.y + ab * v1.y;
                acc[r].z += aa * v0.z + ab * v1.z;
                acc[r].w += aa * v0.w + ab * v1.w;
            }
        }
    }
    if (t < off1) {
        int s0 = g_ssrc[t];
        float2 as0 = als[s0];
        float e00 = as0.x + ad.x; e00 = (e00 > 0.f) ? e00 : SLOPE * e00;
        float e01 = as0.y + ad.y; e01 = (e01 > 0.f) ? e01 : SLOPE * e01;
        float a00 = __expf(e00) * inv0, a01 = __expf(e01) * inv1;
        const float4* xr0 = xw + (size_t)s0 * HC4;
#pragma unroll
        for (int r = 0; r < NACC; r++) {
            int c4 = cbase + lane + 32 * r;
            if (lane + 32 * r < PART4) {
                float aa = (c4 < C4) ? a00 : a01;
                float4 v0 = __ldg(&xr0[c4]);
                acc[r].x += aa * v0.x; acc[r].y += aa * v0.y;
                acc[r].z += aa * v0.z; acc[r].w += aa * v0.w;
            }
        }
    }

    // epilogue: bias (+relu for layer 1), single store
    const float4* b4 = (const float4*)bias;
#pragma unroll
    for (int r = 0; r < NACC; r++) {
        int c4 = cbase + lane + 32 * r;
        if (lane + 32 * r < PART4) {
            float4 b = b4[c4];
            float4 v;
            if (LAYER == 1) {
                v.x = fmaxf(acc[r].x + b.x, 0.f);
                v.y = fmaxf(acc[r].y + b.y, 0.f);
                v.z = fmaxf(acc[r].z + b.z, 0.f);
                v.w = fmaxf(acc[r].w + b.w, 0.f);
            } else {
                v.x = acc[r].x + b.x; v.y = acc[r].y + b.y;
                v.z = acc[r].z + b.z; v.w = acc[r].w + b.w;
            }
            outv[(size_t)d * HC4 + c4] = v;
        }
    }
}

// ---------------- fused GraphNorm + relu + mean-pool (batch sorted -> contiguous graphs) ----------------
// grid (NGRAPH, 2): block handles graph g, channels [blockIdx.y*100, +100). 4-way MLP unroll.
__global__ __launch_bounds__(128) void graphnorm_kernel(
    const float* __restrict__ gn_ms, const float* __restrict__ gn_w, const float* __restrict__ gn_b)
{
    int g = blockIdx.x;
    int c = blockIdx.y * (HC2 / 2) + threadIdx.x;
    if (threadIdx.x >= HC2 / 2) return;
    int n0 = g_gstart[g];
    float cntf = g_cnt[g];
    int n1 = n0 + (int)cntf;
    const float* h = (const float*)g_c2;

    float s0 = 0.f, s1 = 0.f, s2 = 0.f, s3 = 0.f;
    int n = n0;
    for (; n + 3 < n1; n += 4) {
        s0 += h[(size_t)(n + 0) * HC2 + c];
        s1 += h[(size_t)(n + 1) * HC2 + c];
        s2 += h[(size_t)(n + 2) * HC2 + c];
        s3 += h[(size_t)(n + 3) * HC2 + c];
    }
    for (; n < n1; n++) s0 += h[(size_t)n * HC2 + c];
    float mean_ms = ((s0 + s1) + (s2 + s3)) / cntf * gn_ms[c];

    float v0 = 0.f, v1 = 0.f, v2 = 0.f, v3 = 0.f;
    n = n0;
    for (; n + 3 < n1; n += 4) {
        float t0 = h[(size_t)(n + 0) * HC2 + c] - mean_ms;
        float t1 = h[(size_t)(n + 1) * HC2 + c] - mean_ms;
        float t2 = h[(size_t)(n + 2) * HC2 + c] - mean_ms;
        float t3 = h[(size_t)(n + 3) * HC2 + c] - mean_ms;
        v0 += t0 * t0; v1 += t1 * t1; v2 += t2 * t2; v3 += t3 * t3;
    }
    for (; n < n1; n++) { float t = h[(size_t)n * HC2 + c] - mean_ms; v0 += t * t; }
    float scale = rsqrtf(((v0 + v1) + (v2 + v3)) / cntf + EPS_GN);

    float w = gn_w[c], b = gn_b[c];
    float p0 = 0.f, p1 = 0.f, p2 = 0.f, p3 = 0.f;
    n = n0;
    for (; n + 3 < n1; n += 4) {
        p0 += fmaxf(w * ((h[(size_t)(n + 0) * HC2 + c] - mean_ms) * scale) + b, 0.f);
        p1 += fmaxf(w * ((h[(size_t)(n + 1) * HC2 + c] - mean_ms) * scale) + b, 0.f);
        p2 += fmaxf(w * ((h[(size_t)(n + 2) * HC2 + c] - mean_ms) * scale) + b, 0.f);
        p3 += fmaxf(w * ((h[(size_t)(n + 3) * HC2 + c] - mean_ms) * scale) + b, 0.f);
    }
    for (; n < n1; n++)
        p0 += fmaxf(w * ((h[(size_t)n * HC2 + c] - mean_ms) * scale) + b, 0.f);
    g_pool[g * HC2 + c] = (p0 + p1) + (p2 + p3);
}

// ---------------- final: logits = (pool/cnt) @ lin_w + lin_b; sigmoid ----------------
__global__ void final_kernel(const float* __restrict__ lin_w, const float* __restrict__ lin_b,
                             float* __restrict__ out)
{
    int t = threadIdx.x;
    if (t >= NGRAPH * 2) return;
    int g = t / 2, k = t % 2;
    float acc = 0.f;
#pragma unroll 8
    for (int c = 0; c < HC2; c++)
        acc += g_pool[g * HC2 + c] * lin_w[c * 2 + k];
    float logit = acc / g_cnt[g] + lin_b[k];
    out[g * 2 + k] = 1.f / (1.f + __expf(-logit));
}

// ---------------- launch ----------------
extern "C" void kernel_launch(void* const* d_in, const int* in_sizes, int n_in,
                              void* d_out, int out_size)
{
    const float* x      = (const float*)d_in[0];
    const int*   ei     = (const int*)d_in[1];
    const int*   batch  = (const int*)d_in[2];
    const float* W1     = (const float*)d_in[3];
    const float* a_src1 = (const float*)d_in[4];
    const float* a_dst1 = (const float*)d_in[5];
    const float* b1     = (const float*)d_in[6];
    const float* W2     = (const float*)d_in[7];
    const float* a_src2 = (const float*)d_in[8];
    const float* a_dst2 = (const float*)d_in[9];
    const float* b2     = (const float*)d_in[10];
    const float* gn_w   = (const float*)d_in[11];
    const float* gn_b   = (const float*)d_in[12];
    const float* gn_ms  = (const float*)d_in[13];
    const float* lin_w  = (const float*)d_in[14];
    const float* lin_b  = (const float*)d_in[15];
    float*       out    = (float*)d_out;

    // index decode + CSR build + graph offsets
    detect_kernel<<<1, 32>>>(ei);
    convert_idx_kernel<<<(NE_TOT + 255) / 256, 256>>>(ei, batch);
    csr_count_kernel<<<(NE_TOT + 255) / 256, 256>>>();
    scan1_kernel<<<NCHUNK, SCAN_CHUNK>>>();
    scan2_kernel<<<1, 32>>>();
    scan3_kernel<<<(N_NODES + 255) / 256, 256>>>();
    csr_fill_kernel<<<(NE_TOT + 255) / 256, 256>>>();
    counts_kernel<<<(N_NODES + 255) / 256, 256>>>();
    graph_offsets_kernel<<<1, 32>>>();

    // ---- layer 1 ----
    {
        dim3 grid((HC1 + BN - 1) / BN, (N_NODES + BM - 1) / BM);
        gemm_kernel<1><<<grid, 256>>>(x, W1);
    }
    attn_logits_kernel<1><<<(N_NODES * HEADS + 255) / 256, 256>>>(a_src1, a_dst1);
    attn_aggr_kernel<1><<<(N_NODES * 2 * 32 + 255) / 256, 256>>>(b1);

    // ---- layer 2 ----
    {
        dim3 grid((HC2 + BN - 1) / BN, (N_NODES + BM - 1) / BM);
        gemm_kernel<2><<<grid, 256>>>(nullptr, W2);
    }
    attn_logits_kernel<2><<<(N_NODES * HEADS + 255) / 256, 256>>>(a_src2, a_dst2);
    attn_aggr_kernel<2><<<(N_NODES * 2 * 32 + 255) / 256, 256>>>(b2);

    // ---- graphnorm + pool + head ----
    {
        dim3 grid(NGRAPH, 2);
        graphnorm_kernel<<<grid, 128>>>(gn_ms, gn_w, gn_b);
    }
    final_kernel<<<1, 128>>>(lin_w, lin_b, out);
}